// round 5
// baseline (speedup 1.0000x reference)
#include <cuda_runtime.h>
#include <math.h>

#define NLVL 16
#define TBLSZ (1u << 19)
#define HMASK (TBLSZ - 1u)

typedef unsigned long long ull;

struct LvlParams {
    float    scale[NLVL];
    int      res[NLVL];
    unsigned densemask;
};

// Layer-1 weights transposed to [j][i]; pairs (i, i+1) contiguous: read as
// 16B uniform constant loads (LDCU.128), feeding two fma.rn.f32x2 each.
__constant__ __align__(16) float c_dw1t[64 * 32];
__constant__ __align__(16) float c_fw1t[64 * 32];
// Layer-2 weights pre-interleaved: w2a[j]=(dw2[j], fw2[j][0]), w2b[j]=(fw2[j][1], fw2[j][2]).
__constant__ __align__(16) float c_w2a[128];
__constant__ __align__(16) float c_w2b[128];

__device__ __align__(16) float g_wscratch[4352];

__global__ void prep_weights_kernel(const float* __restrict__ dw1,
                                    const float* __restrict__ fw1,
                                    const float* __restrict__ dw2,
                                    const float* __restrict__ fw2)
{
    int t = blockIdx.x * 256 + threadIdx.x;   // 0..2047
    if (t < 2048) {
        int i = t & 31, j = t >> 5;           // t = j*32 + i
        g_wscratch[t]        = dw1[i * 64 + j];
        g_wscratch[2048 + t] = fw1[i * 64 + j];
    }
    if (t < 64) {
        g_wscratch[4096 + 2 * t + 0] = dw2[t];
        g_wscratch[4096 + 2 * t + 1] = fw2[3 * t + 0];
        g_wscratch[4224 + 2 * t + 0] = fw2[3 * t + 1];
        g_wscratch[4224 + 2 * t + 1] = fw2[3 * t + 2];
    }
}

__device__ __forceinline__ ull pack2(float lo, float hi) {
    ull r;
    asm("mov.b64 %0, {%1, %2};" : "=l"(r) : "f"(lo), "f"(hi));
    return r;
}
__device__ __forceinline__ float2 unpack2(ull v) {
    float2 r;
    asm("mov.b64 {%0, %1}, %2;" : "=f"(r.x), "=f"(r.y) : "l"(v));
    return r;
}
__device__ __forceinline__ ull fma2(ull a, ull b, ull c) {
    ull d;
    asm("fma.rn.f32x2 %0, %1, %2, %3;" : "=l"(d) : "l"(a), "l"(b), "l"(c));
    return d;
}

__global__ void __launch_bounds__(256)
nerf_field_kernel(const float* __restrict__ points,
                  const float* __restrict__ table,
                  float* __restrict__ out,
                  int N, LvlParams P)
{
    int gid = blockIdx.x * 256 + threadIdx.x;
    if (gid >= N) return;

    float x = fminf(fmaxf((points[gid * 3 + 0] + 1.0f) * 0.5f, 0.0f), 1.0f);
    float y = fminf(fmaxf((points[gid * 3 + 1] + 1.0f) * 0.5f, 0.0f), 1.0f);
    float z = fminf(fmaxf((points[gid * 3 + 2] + 1.0f) * 0.5f, 0.0f), 1.0f);

    ull encp[16];   // enc as 16 packed float pairs (one per level)

    #pragma unroll
    for (int l = 0; l < NLVL; l++) {
        const float sc = P.scale[l];
        const int   R  = P.res[l];
        const bool  dense = (P.densemask >> l) & 1u;

        float px = x * sc + 0.5f;
        float py = y * sc + 0.5f;
        float pz = z * sc + 0.5f;
        float fx = floorf(px), fy = floorf(py), fz = floorf(pz);
        float wx = px - fx,    wy = py - fy,    wz = pz - fz;
        int ix = (int)fx, iy = (int)fy, iz = (int)fz;

        unsigned x0 = (unsigned)min(max(ix,     0), R - 1);
        unsigned x1 = (unsigned)min(max(ix + 1, 0), R - 1);
        int y0 = min(max(iy,     0), R - 1), y1 = min(max(iy + 1, 0), R - 1);
        int z0 = min(max(iz,     0), R - 1), z1 = min(max(iz + 1, 0), R - 1);

        // x uses prime 1: x-adjacent entries are index-adjacent -> pairable
        // into one aligned 16B block (second load predicated, ~50% of lanes).
        unsigned hy[2], hz[2];
        if (dense) {
            hy[0] = (unsigned)(y0 * R);      hy[1] = (unsigned)(y1 * R);
            hz[0] = (unsigned)(z0 * R * R);  hz[1] = (unsigned)(z1 * R * R);
        } else {
            hy[0] = (unsigned)y0 * 2654435761u;  hy[1] = (unsigned)y1 * 2654435761u;
            hz[0] = (unsigned)z0 * 805459861u;   hz[1] = (unsigned)z1 * 805459861u;
        }

        const float4* t4 = reinterpret_cast<const float4*>(table) + (size_t)l * (TBLSZ / 2);

        float wwy[2] = {1.0f - wy, wy};
        float wwz[2] = {1.0f - wz, wz};
        float wA = 1.0f - wx, wB = wx;
        ull f01 = 0ull;

        #pragma unroll
        for (int yi = 0; yi < 2; yi++) {
            #pragma unroll
            for (int zi = 0; zi < 2; zi++) {
                unsigned h, iA, iB;
                if (dense) {
                    h  = hy[yi] + hz[zi];
                    iA = h + x0;
                    iB = h + x1;
                } else {
                    h  = hy[yi] ^ hz[zi];
                    iA = (h ^ x0) & HMASK;
                    iB = (h ^ x1) & HMASK;
                }
                unsigned pA = iA >> 1, pB = iB >> 1;
                float4 qA = __ldg(t4 + pA);
                float4 qB = qA;
                if (pB != pA) qB = __ldg(t4 + pB);   // predicated extra load

                ull gA = (iA & 1) ? pack2(qA.z, qA.w) : pack2(qA.x, qA.y);
                ull gB = (iB & 1) ? pack2(qB.z, qB.w) : pack2(qB.x, qB.y);

                float wyz = wwy[yi] * wwz[zi];
                float wAyz = wyz * wA, wByz = wyz * wB;
                f01 = fma2(pack2(wAyz, wAyz), gA, f01);
                f01 = fma2(pack2(wByz, wByz), gB, f01);
            }
        }
        encp[l] = f01;
    }

    // Two 2-layer bias-free MLPs; layer-1 weights read as 16B uniform
    // constant loads (2 packed pairs per load), packed-pair FMAs throughout.
    const ulonglong2* wd4 = reinterpret_cast<const ulonglong2*>(c_dw1t);  // [64][8]
    const ulonglong2* wf4 = reinterpret_cast<const ulonglong2*>(c_fw1t);
    const ull* w2a = reinterpret_cast<const ull*>(c_w2a);                 // [64]
    const ull* w2b = reinterpret_cast<const ull*>(c_w2b);

    ull dc = 0ull;   // (density_acc, color0)
    ull cc = 0ull;   // (color1, color2)
    #pragma unroll 4
    for (int j = 0; j < 64; j++) {
        ull s2 = 0ull, t2 = 0ull;
        #pragma unroll
        for (int k = 0; k < 8; k++) {
            ulonglong2 wv = wd4[j * 8 + k];
            ulonglong2 fv = wf4[j * 8 + k];
            s2 = fma2(encp[2 * k + 0], wv.x, s2);
            t2 = fma2(encp[2 * k + 0], fv.x, t2);
            s2 = fma2(encp[2 * k + 1], wv.y, s2);
            t2 = fma2(encp[2 * k + 1], fv.y, t2);
        }
        float2 sv = unpack2(s2), tv = unpack2(t2);
        float s = fmaxf(sv.x + sv.y, 0.0f);
        float t = fmaxf(tv.x + tv.y, 0.0f);
        dc = fma2(pack2(s, t), w2a[j], dc);
        cc = fma2(pack2(t, t), w2b[j], cc);
    }

    float2 dcv = unpack2(dc);
    float2 ccv = unpack2(cc);
    float dacc = dcv.x, c0 = dcv.y, c1 = ccv.x, c2 = ccv.y;

    float density = fmaxf(dacc, 0.0f) + log1pf(expf(-fabsf(dacc)));
    float r0 = 1.0f / (1.0f + expf(-c0));
    float r1 = 1.0f / (1.0f + expf(-c1));
    float r2 = 1.0f / (1.0f + expf(-c2));

    out[gid * 3 + 0] = r0;
    out[gid * 3 + 1] = r1;
    out[gid * 3 + 2] = r2;
    out[(size_t)3 * N + gid] = density;
}

extern "C" void kernel_launch(void* const* d_in, const int* in_sizes, int n_in,
                              void* d_out, int out_size)
{
    const float* points = (const float*)d_in[0];
    const float* table  = (const float*)d_in[1];
    const float* dw1    = (const float*)d_in[2];
    const float* dw2    = (const float*)d_in[3];
    const float* fw1    = (const float*)d_in[4];
    const float* fw2    = (const float*)d_in[5];
    int N = in_sizes[0] / 3;

    prep_weights_kernel<<<8, 256>>>(dw1, fw1, dw2, fw2);
    void* src = nullptr;
    cudaGetSymbolAddress(&src, g_wscratch);
    cudaMemcpyToSymbolAsync(c_dw1t, src, 2048 * sizeof(float), 0,
                            cudaMemcpyDeviceToDevice, 0);
    cudaMemcpyToSymbolAsync(c_fw1t, (const char*)src + 2048 * sizeof(float),
                            2048 * sizeof(float), 0,
                            cudaMemcpyDeviceToDevice, 0);
    cudaMemcpyToSymbolAsync(c_w2a, (const char*)src + 4096 * sizeof(float),
                            128 * sizeof(float), 0,
                            cudaMemcpyDeviceToDevice, 0);
    cudaMemcpyToSymbolAsync(c_w2b, (const char*)src + 4224 * sizeof(float),
                            128 * sizeof(float), 0,
                            cudaMemcpyDeviceToDevice, 0);

    LvlParams P;
    P.densemask = 0u;
    for (int l = 0; l < NLVL; l++) {
        double sc = 16.0 * pow(1.447269237440378, (double)l) - 1.0;
        int res = (int)ceil(sc) + 1;
        P.scale[l] = (float)sc;
        P.res[l] = res;
        long long r3 = (long long)res * res * res;
        if (r3 <= (long long)TBLSZ) P.densemask |= (1u << l);
    }

    int blocks = (N + 255) / 256;
    nerf_field_kernel<<<blocks, 256>>>(points, table, (float*)d_out, N, P);
}

// round 6
// speedup vs baseline: 1.0080x; 1.0080x over previous
#include <cuda_runtime.h>
#include <math.h>

#define NLVL 16
#define TBLSZ (1u << 19)
#define HMASK (TBLSZ - 1u)

typedef unsigned long long ull;

struct LvlParams {
    float    scale[NLVL];
    int      res[NLVL];
    unsigned densemask;
};

// Layer-1 weights transposed to [j][i]; pairs (i, i+1) contiguous (uniform
// constant-port loads). Layer-2 pre-interleaved pairs.
__constant__ __align__(16) float c_dw1t[64 * 32];
__constant__ __align__(16) float c_fw1t[64 * 32];
__constant__ __align__(16) float c_w2a[128];
__constant__ __align__(16) float c_w2b[128];

__device__ __align__(16) float g_wscratch[4352];

__global__ void prep_weights_kernel(const float* __restrict__ dw1,
                                    const float* __restrict__ fw1,
                                    const float* __restrict__ dw2,
                                    const float* __restrict__ fw2)
{
    int t = blockIdx.x * 256 + threadIdx.x;   // 0..2047
    if (t < 2048) {
        int i = t & 31, j = t >> 5;           // t = j*32 + i
        g_wscratch[t]        = dw1[i * 64 + j];
        g_wscratch[2048 + t] = fw1[i * 64 + j];
    }
    if (t < 64) {
        g_wscratch[4096 + 2 * t + 0] = dw2[t];
        g_wscratch[4096 + 2 * t + 1] = fw2[3 * t + 0];
        g_wscratch[4224 + 2 * t + 0] = fw2[3 * t + 1];
        g_wscratch[4224 + 2 * t + 1] = fw2[3 * t + 2];
    }
}

__device__ __forceinline__ ull pack2(float lo, float hi) {
    ull r;
    asm("mov.b64 %0, {%1, %2};" : "=l"(r) : "f"(lo), "f"(hi));
    return r;
}
__device__ __forceinline__ float2 unpack2(ull v) {
    float2 r;
    asm("mov.b64 {%0, %1}, %2;" : "=f"(r.x), "=f"(r.y) : "l"(v));
    return r;
}
__device__ __forceinline__ ull fma2(ull a, ull b, ull c) {
    ull d;
    asm("fma.rn.f32x2 %0, %1, %2, %3;" : "=l"(d) : "l"(a), "l"(b), "l"(c));
    return d;
}
__device__ __forceinline__ ull add2(ull a, ull b) {
    ull d;
    asm("add.rn.f32x2 %0, %1, %2;" : "=l"(d) : "l"(a), "l"(b));
    return d;
}

// 3 blocks/SM cap -> ~85 regs available: lets ptxas batch gathers across
// levels and keep multiple FMA chains in flight (kernel is latency-bound).
__global__ void __launch_bounds__(256, 3)
nerf_field_kernel(const float* __restrict__ points,
                  const float* __restrict__ table,
                  float* __restrict__ out,
                  int N, LvlParams P)
{
    int gid = blockIdx.x * 256 + threadIdx.x;
    if (gid >= N) return;

    float x = fminf(fmaxf((points[gid * 3 + 0] + 1.0f) * 0.5f, 0.0f), 1.0f);
    float y = fminf(fmaxf((points[gid * 3 + 1] + 1.0f) * 0.5f, 0.0f), 1.0f);
    float z = fminf(fmaxf((points[gid * 3 + 2] + 1.0f) * 0.5f, 0.0f), 1.0f);

    ull encp[16];   // enc as 16 packed float pairs (one per level)

    #pragma unroll
    for (int l = 0; l < NLVL; l++) {
        const float sc = P.scale[l];
        const int   R  = P.res[l];
        const bool  dense = (P.densemask >> l) & 1u;

        float px = x * sc + 0.5f;
        float py = y * sc + 0.5f;
        float pz = z * sc + 0.5f;
        float fx = floorf(px), fy = floorf(py), fz = floorf(pz);
        float wx = px - fx,    wy = py - fy,    wz = pz - fz;
        int ix = (int)fx, iy = (int)fy, iz = (int)fz;

        unsigned x0 = (unsigned)min(max(ix,     0), R - 1);
        unsigned x1 = (unsigned)min(max(ix + 1, 0), R - 1);
        int y0 = min(max(iy,     0), R - 1), y1 = min(max(iy + 1, 0), R - 1);
        int z0 = min(max(iz,     0), R - 1), z1 = min(max(iz + 1, 0), R - 1);

        // x uses prime 1: x-adjacent entries are index-adjacent -> pairable
        // into one aligned 16B block (second load predicated, ~50% of lanes).
        unsigned hy[2], hz[2];
        if (dense) {
            hy[0] = (unsigned)(y0 * R);      hy[1] = (unsigned)(y1 * R);
            hz[0] = (unsigned)(z0 * R * R);  hz[1] = (unsigned)(z1 * R * R);
        } else {
            hy[0] = (unsigned)y0 * 2654435761u;  hy[1] = (unsigned)y1 * 2654435761u;
            hz[0] = (unsigned)z0 * 805459861u;   hz[1] = (unsigned)z1 * 805459861u;
        }

        const float4* t4 = reinterpret_cast<const float4*>(table) + (size_t)l * (TBLSZ / 2);

        float wwy[2] = {1.0f - wy, wy};
        float wwz[2] = {1.0f - wz, wz};
        float wA = 1.0f - wx, wB = wx;
        ull f01a = 0ull, f01b = 0ull;   // split accumulators (shorter chains)

        #pragma unroll
        for (int yi = 0; yi < 2; yi++) {
            #pragma unroll
            for (int zi = 0; zi < 2; zi++) {
                unsigned h, iA, iB;
                if (dense) {
                    h  = hy[yi] + hz[zi];
                    iA = h + x0;
                    iB = h + x1;
                } else {
                    h  = hy[yi] ^ hz[zi];
                    iA = (h ^ x0) & HMASK;
                    iB = (h ^ x1) & HMASK;
                }
                unsigned pA = iA >> 1, pB = iB >> 1;
                float4 qA = __ldg(t4 + pA);
                float4 qB = qA;
                if (pB != pA) qB = __ldg(t4 + pB);   // predicated extra load

                ull gA = (iA & 1) ? pack2(qA.z, qA.w) : pack2(qA.x, qA.y);
                ull gB = (iB & 1) ? pack2(qB.z, qB.w) : pack2(qB.x, qB.y);

                float wyz = wwy[yi] * wwz[zi];
                float wAyz = wyz * wA, wByz = wyz * wB;
                f01a = fma2(pack2(wAyz, wAyz), gA, f01a);
                f01b = fma2(pack2(wByz, wByz), gB, f01b);
            }
        }
        encp[l] = add2(f01a, f01b);
    }

    // Two 2-layer bias-free MLPs; packed-pair FMAs, chains split for ILP.
    const ulonglong2* wd4 = reinterpret_cast<const ulonglong2*>(c_dw1t);  // [64][8]
    const ulonglong2* wf4 = reinterpret_cast<const ulonglong2*>(c_fw1t);
    const ull* w2a = reinterpret_cast<const ull*>(c_w2a);                 // [64]
    const ull* w2b = reinterpret_cast<const ull*>(c_w2b);

    ull dc0 = 0ull, dc1 = 0ull;   // (density_acc, color0) partials
    ull cc0 = 0ull, cc1 = 0ull;   // (color1, color2) partials
    #pragma unroll 4
    for (int j = 0; j < 64; j++) {
        ull s2a = 0ull, s2b = 0ull, t2a = 0ull, t2b = 0ull;
        #pragma unroll
        for (int k = 0; k < 4; k++) {
            ulonglong2 wv0 = wd4[j * 8 + 2 * k + 0];
            ulonglong2 fv0 = wf4[j * 8 + 2 * k + 0];
            ulonglong2 wv1 = wd4[j * 8 + 2 * k + 1];
            ulonglong2 fv1 = wf4[j * 8 + 2 * k + 1];
            s2a = fma2(encp[4 * k + 0], wv0.x, s2a);
            t2a = fma2(encp[4 * k + 0], fv0.x, t2a);
            s2b = fma2(encp[4 * k + 1], wv0.y, s2b);
            t2b = fma2(encp[4 * k + 1], fv0.y, t2b);
            s2a = fma2(encp[4 * k + 2], wv1.x, s2a);
            t2a = fma2(encp[4 * k + 2], fv1.x, t2a);
            s2b = fma2(encp[4 * k + 3], wv1.y, s2b);
            t2b = fma2(encp[4 * k + 3], fv1.y, t2b);
        }
        float2 sv = unpack2(add2(s2a, s2b));
        float2 tv = unpack2(add2(t2a, t2b));
        float s = fmaxf(sv.x + sv.y, 0.0f);
        float t = fmaxf(tv.x + tv.y, 0.0f);
        if (j & 1) {
            dc1 = fma2(pack2(s, t), w2a[j], dc1);
            cc1 = fma2(pack2(t, t), w2b[j], cc1);
        } else {
            dc0 = fma2(pack2(s, t), w2a[j], dc0);
            cc0 = fma2(pack2(t, t), w2b[j], cc0);
        }
    }

    float2 dcv = unpack2(add2(dc0, dc1));
    float2 ccv = unpack2(add2(cc0, cc1));
    float dacc = dcv.x, c0 = dcv.y, c1 = ccv.x, c2 = ccv.y;

    float density = fmaxf(dacc, 0.0f) + log1pf(expf(-fabsf(dacc)));
    float r0 = 1.0f / (1.0f + expf(-c0));
    float r1 = 1.0f / (1.0f + expf(-c1));
    float r2 = 1.0f / (1.0f + expf(-c2));

    out[gid * 3 + 0] = r0;
    out[gid * 3 + 1] = r1;
    out[gid * 3 + 2] = r2;
    out[(size_t)3 * N + gid] = density;
}

extern "C" void kernel_launch(void* const* d_in, const int* in_sizes, int n_in,
                              void* d_out, int out_size)
{
    const float* points = (const float*)d_in[0];
    const float* table  = (const float*)d_in[1];
    const float* dw1    = (const float*)d_in[2];
    const float* dw2    = (const float*)d_in[3];
    const float* fw1    = (const float*)d_in[4];
    const float* fw2    = (const float*)d_in[5];
    int N = in_sizes[0] / 3;

    prep_weights_kernel<<<8, 256>>>(dw1, fw1, dw2, fw2);
    void* src = nullptr;
    cudaGetSymbolAddress(&src, g_wscratch);
    cudaMemcpyToSymbolAsync(c_dw1t, src, 2048 * sizeof(float), 0,
                            cudaMemcpyDeviceToDevice, 0);
    cudaMemcpyToSymbolAsync(c_fw1t, (const char*)src + 2048 * sizeof(float),
                            2048 * sizeof(float), 0,
                            cudaMemcpyDeviceToDevice, 0);
    cudaMemcpyToSymbolAsync(c_w2a, (const char*)src + 4096 * sizeof(float),
                            128 * sizeof(float), 0,
                            cudaMemcpyDeviceToDevice, 0);
    cudaMemcpyToSymbolAsync(c_w2b, (const char*)src + 4224 * sizeof(float),
                            128 * sizeof(float), 0,
                            cudaMemcpyDeviceToDevice, 0);

    LvlParams P;
    P.densemask = 0u;
    for (int l = 0; l < NLVL; l++) {
        double sc = 16.0 * pow(1.447269237440378, (double)l) - 1.0;
        int res = (int)ceil(sc) + 1;
        P.scale[l] = (float)sc;
        P.res[l] = res;
        long long r3 = (long long)res * res * res;
        if (r3 <= (long long)TBLSZ) P.densemask |= (1u << l);
    }

    int blocks = (N + 255) / 256;
    nerf_field_kernel<<<blocks, 256>>>(points, table, (float*)d_out, N, P);
}

// round 7
// speedup vs baseline: 1.0466x; 1.0383x over previous
#include <cuda_runtime.h>
#include <cuda_bf16.h>
#include <math.h>

#define NLVL 16
#define NDENSE 5
#define TBLSZ (1u << 19)
#define HMASK (TBLSZ - 1u)

typedef unsigned long long ull;

struct LvlParams {
    float scale[NLVL];
    int   res[NLVL];
    int   denseBase[NDENSE];   // cell-offset of each dense level
};

// ---- constant-memory MLP weights (layer1 transposed [j][i], layer2 interleaved)
__constant__ __align__(16) float c_dw1t[64 * 32];
__constant__ __align__(16) float c_fw1t[64 * 32];
__constant__ __align__(16) float c_w2a[128];
__constant__ __align__(16) float c_w2b[128];

__device__ __align__(16) float g_wscratch[4352];

// Duplicated-corner dense table: per cell, 8 corners x bf16x2 = 32B.
// Levels 0-4: 4096+13824+39304+117649+357911 = 532784 cells.
#define DENSE_CELLS 532784
__device__ __align__(16) unsigned g_dense[DENSE_CELLS * 8];

__global__ void prep_weights_kernel(const float* __restrict__ dw1,
                                    const float* __restrict__ fw1,
                                    const float* __restrict__ dw2,
                                    const float* __restrict__ fw2)
{
    int t = blockIdx.x * 256 + threadIdx.x;   // 0..2047
    if (t < 2048) {
        int i = t & 31, j = t >> 5;           // t = j*32 + i
        g_wscratch[t]        = dw1[i * 64 + j];
        g_wscratch[2048 + t] = fw1[i * 64 + j];
    }
    if (t < 64) {
        g_wscratch[4096 + 2 * t + 0] = dw2[t];
        g_wscratch[4096 + 2 * t + 1] = fw2[3 * t + 0];
        g_wscratch[4224 + 2 * t + 0] = fw2[3 * t + 1];
        g_wscratch[4224 + 2 * t + 1] = fw2[3 * t + 2];
    }
}

// Build the duplicated-corner bf16 dense table (runs every replay: deterministic).
__global__ void build_dense_kernel(const float* __restrict__ table, LvlParams P)
{
    int id = blockIdx.x * 256 + threadIdx.x;
    if (id >= DENSE_CELLS) return;

    int l = 0;
    #pragma unroll
    for (int k = 1; k < NDENSE; k++)
        if (id >= P.denseBase[k]) l = k;

    int cid = id - P.denseBase[l];
    int R = P.res[l];
    int cx = cid % R;
    int t  = cid / R;
    int cy = t % R;
    int cz = t / R;

    const float2* tl = reinterpret_cast<const float2*>(table) + (size_t)l * TBLSZ;

    unsigned o[8];
    #pragma unroll
    for (int c = 0; c < 8; c++) {
        int xi = (c >> 2) & 1, yi = (c >> 1) & 1, zi = c & 1;
        int gx = min(cx + xi, R - 1);
        int gy = min(cy + yi, R - 1);
        int gz = min(cz + zi, R - 1);
        float2 v = tl[gx + R * (gy + R * gz)];
        __nv_bfloat162 b = __floats2bfloat162_rn(v.x, v.y);  // .x -> low bits
        o[c] = *reinterpret_cast<unsigned*>(&b);
    }
    uint4* dst = reinterpret_cast<uint4*>(g_dense) + (size_t)id * 2;
    dst[0] = make_uint4(o[0], o[1], o[2], o[3]);
    dst[1] = make_uint4(o[4], o[5], o[6], o[7]);
}

__device__ __forceinline__ ull pack2(float lo, float hi) {
    ull r;
    asm("mov.b64 %0, {%1, %2};" : "=l"(r) : "f"(lo), "f"(hi));
    return r;
}
__device__ __forceinline__ float2 unpack2(ull v) {
    float2 r;
    asm("mov.b64 {%0, %1}, %2;" : "=f"(r.x), "=f"(r.y) : "l"(v));
    return r;
}
__device__ __forceinline__ ull fma2(ull a, ull b, ull c) {
    ull d;
    asm("fma.rn.f32x2 %0, %1, %2, %3;" : "=l"(d) : "l"(a), "l"(b), "l"(c));
    return d;
}
__device__ __forceinline__ ull add2(ull a, ull b) {
    ull d;
    asm("add.rn.f32x2 %0, %1, %2;" : "=l"(d) : "l"(a), "l"(b));
    return d;
}
// bf16x2 word -> packed f32x2 pair (lo, hi): bf16->f32 is a 16-bit shift.
__device__ __forceinline__ ull unpbf(unsigned u) {
    return pack2(__uint_as_float(u << 16), __uint_as_float(u & 0xFFFF0000u));
}
__device__ __forceinline__ ull bc(float w) { return pack2(w, w); }

__global__ void __launch_bounds__(256, 3)
nerf_field_kernel(const float* __restrict__ points,
                  const float* __restrict__ table,
                  float* __restrict__ out,
                  int N, LvlParams P)
{
    int gid = blockIdx.x * 256 + threadIdx.x;
    if (gid >= N) return;

    float x = fminf(fmaxf((points[gid * 3 + 0] + 1.0f) * 0.5f, 0.0f), 1.0f);
    float y = fminf(fmaxf((points[gid * 3 + 1] + 1.0f) * 0.5f, 0.0f), 1.0f);
    float z = fminf(fmaxf((points[gid * 3 + 2] + 1.0f) * 0.5f, 0.0f), 1.0f);

    ull encp[16];

    // ---- dense levels 0..4: one 32B duplicated-corner record per cell ----
    #pragma unroll
    for (int l = 0; l < NDENSE; l++) {
        const float sc = P.scale[l];
        const int   R  = P.res[l];
        float px = x * sc + 0.5f, py = y * sc + 0.5f, pz = z * sc + 0.5f;
        float fx = floorf(px), fy = floorf(py), fz = floorf(pz);
        float wx = px - fx,    wy = py - fy,    wz = pz - fz;
        int ix = (int)fx, iy = (int)fy, iz = (int)fz;   // always in [0, R-1]
        int cell = ix + R * (iy + R * iz);

        const uint4* rec = reinterpret_cast<const uint4*>(g_dense)
                         + (((size_t)(P.denseBase[l] + cell)) << 1);
        uint4 q0 = __ldg(rec);
        uint4 q1 = __ldg(rec + 1);

        float wx0 = 1.0f - wx, wy0 = 1.0f - wy, wz0 = 1.0f - wz;
        float w00 = wy0 * wz0, w01 = wy0 * wz, w10 = wy * wz0, w11 = wy * wz;

        ull a = 0ull, b = 0ull;
        a = fma2(bc(wx0 * w00), unpbf(q0.x), a);
        b = fma2(bc(wx0 * w01), unpbf(q0.y), b);
        a = fma2(bc(wx0 * w10), unpbf(q0.z), a);
        b = fma2(bc(wx0 * w11), unpbf(q0.w), b);
        a = fma2(bc(wx  * w00), unpbf(q1.x), a);
        b = fma2(bc(wx  * w01), unpbf(q1.y), b);
        a = fma2(bc(wx  * w10), unpbf(q1.z), a);
        b = fma2(bc(wx  * w11), unpbf(q1.w), b);
        encp[l] = add2(a, b);
    }

    // ---- hashed levels 5..15 ----
    #pragma unroll
    for (int l = NDENSE; l < NLVL; l++) {
        const float sc = P.scale[l];
        const int   R  = P.res[l];

        float px = x * sc + 0.5f, py = y * sc + 0.5f, pz = z * sc + 0.5f;
        float fx = floorf(px), fy = floorf(py), fz = floorf(pz);
        float wx = px - fx,    wy = py - fy,    wz = pz - fz;
        int ix = (int)fx, iy = (int)fy, iz = (int)fz;   // >= 0 always

        unsigned x0 = (unsigned)ix;
        unsigned x1 = (unsigned)min(ix + 1, R - 1);     // only upper clamp needed
        unsigned hy0 = (unsigned)iy * 2654435761u;
        unsigned hy1 = (unsigned)min(iy + 1, R - 1) * 2654435761u;
        unsigned hz0 = (unsigned)iz * 805459861u;
        unsigned hz1 = (unsigned)min(iz + 1, R - 1) * 805459861u;

        const float4* t4 = reinterpret_cast<const float4*>(table) + (size_t)l * (TBLSZ / 2);

        float wwy[2] = {1.0f - wy, wy};
        float wwz[2] = {1.0f - wz, wz};
        unsigned hyv[2] = {hy0, hy1};
        unsigned hzv[2] = {hz0, hz1};
        float wA = 1.0f - wx, wB = wx;
        ull f01a = 0ull, f01b = 0ull;

        #pragma unroll
        for (int yi = 0; yi < 2; yi++) {
            #pragma unroll
            for (int zi = 0; zi < 2; zi++) {
                unsigned h  = hyv[yi] ^ hzv[zi];
                unsigned iA = (h ^ x0) & HMASK;
                unsigned iB = (h ^ x1) & HMASK;
                unsigned pA = iA >> 1, pB = iB >> 1;
                float4 qA = __ldg(t4 + pA);
                float4 qB = qA;
                if (pB != pA) qB = __ldg(t4 + pB);   // predicated extra load

                ull gA = (iA & 1) ? pack2(qA.z, qA.w) : pack2(qA.x, qA.y);
                ull gB = (iB & 1) ? pack2(qB.z, qB.w) : pack2(qB.x, qB.y);

                float wyz = wwy[yi] * wwz[zi];
                f01a = fma2(bc(wyz * wA), gA, f01a);
                f01b = fma2(bc(wyz * wB), gB, f01b);
            }
        }
        encp[l] = add2(f01a, f01b);
    }

    // ---- two 2-layer bias-free MLPs (constant-port weights, f32x2 FMAs) ----
    const ulonglong2* wd4 = reinterpret_cast<const ulonglong2*>(c_dw1t);
    const ulonglong2* wf4 = reinterpret_cast<const ulonglong2*>(c_fw1t);
    const ull* w2a = reinterpret_cast<const ull*>(c_w2a);
    const ull* w2b = reinterpret_cast<const ull*>(c_w2b);

    ull dc0 = 0ull, dc1 = 0ull;
    ull cc0 = 0ull, cc1 = 0ull;
    #pragma unroll 4
    for (int j = 0; j < 64; j++) {
        ull s2a = 0ull, s2b = 0ull, t2a = 0ull, t2b = 0ull;
        #pragma unroll
        for (int k = 0; k < 4; k++) {
            ulonglong2 wv0 = wd4[j * 8 + 2 * k + 0];
            ulonglong2 fv0 = wf4[j * 8 + 2 * k + 0];
            ulonglong2 wv1 = wd4[j * 8 + 2 * k + 1];
            ulonglong2 fv1 = wf4[j * 8 + 2 * k + 1];
            s2a = fma2(encp[4 * k + 0], wv0.x, s2a);
            t2a = fma2(encp[4 * k + 0], fv0.x, t2a);
            s2b = fma2(encp[4 * k + 1], wv0.y, s2b);
            t2b = fma2(encp[4 * k + 1], fv0.y, t2b);
            s2a = fma2(encp[4 * k + 2], wv1.x, s2a);
            t2a = fma2(encp[4 * k + 2], fv1.x, t2a);
            s2b = fma2(encp[4 * k + 3], wv1.y, s2b);
            t2b = fma2(encp[4 * k + 3], fv1.y, t2b);
        }
        float2 sv = unpack2(add2(s2a, s2b));
        float2 tv = unpack2(add2(t2a, t2b));
        float s = fmaxf(sv.x + sv.y, 0.0f);
        float t = fmaxf(tv.x + tv.y, 0.0f);
        if (j & 1) {
            dc1 = fma2(pack2(s, t), w2a[j], dc1);
            cc1 = fma2(pack2(t, t), w2b[j], cc1);
        } else {
            dc0 = fma2(pack2(s, t), w2a[j], dc0);
            cc0 = fma2(pack2(t, t), w2b[j], cc0);
        }
    }

    float2 dcv = unpack2(add2(dc0, dc1));
    float2 ccv = unpack2(add2(cc0, cc1));
    float dacc = dcv.x, c0 = dcv.y, c1 = ccv.x, c2 = ccv.y;

    float density = fmaxf(dacc, 0.0f) + log1pf(expf(-fabsf(dacc)));
    float r0 = 1.0f / (1.0f + expf(-c0));
    float r1 = 1.0f / (1.0f + expf(-c1));
    float r2 = 1.0f / (1.0f + expf(-c2));

    out[gid * 3 + 0] = r0;
    out[gid * 3 + 1] = r1;
    out[gid * 3 + 2] = r2;
    out[(size_t)3 * N + gid] = density;
}

extern "C" void kernel_launch(void* const* d_in, const int* in_sizes, int n_in,
                              void* d_out, int out_size)
{
    const float* points = (const float*)d_in[0];
    const float* table  = (const float*)d_in[1];
    const float* dw1    = (const float*)d_in[2];
    const float* dw2    = (const float*)d_in[3];
    const float* fw1    = (const float*)d_in[4];
    const float* fw2    = (const float*)d_in[5];
    int N = in_sizes[0] / 3;

    LvlParams P;
    int cellBase = 0;
    for (int l = 0; l < NLVL; l++) {
        double sc = 16.0 * pow(1.447269237440378, (double)l) - 1.0;
        int res = (int)ceil(sc) + 1;
        P.scale[l] = (float)sc;
        P.res[l] = res;
        if (l < NDENSE) {
            P.denseBase[l] = cellBase;
            cellBase += res * res * res;
        }
    }

    prep_weights_kernel<<<8, 256>>>(dw1, fw1, dw2, fw2);
    build_dense_kernel<<<(DENSE_CELLS + 255) / 256, 256>>>(table, P);

    void* src = nullptr;
    cudaGetSymbolAddress(&src, g_wscratch);
    cudaMemcpyToSymbolAsync(c_dw1t, src, 2048 * sizeof(float), 0,
                            cudaMemcpyDeviceToDevice, 0);
    cudaMemcpyToSymbolAsync(c_fw1t, (const char*)src + 2048 * sizeof(float),
                            2048 * sizeof(float), 0,
                            cudaMemcpyDeviceToDevice, 0);
    cudaMemcpyToSymbolAsync(c_w2a, (const char*)src + 4096 * sizeof(float),
                            128 * sizeof(float), 0,
                            cudaMemcpyDeviceToDevice, 0);
    cudaMemcpyToSymbolAsync(c_w2b, (const char*)src + 4224 * sizeof(float),
                            128 * sizeof(float), 0,
                            cudaMemcpyDeviceToDevice, 0);

    int blocks = (N + 255) / 256;
    nerf_field_kernel<<<blocks, 256>>>(points, table, (float*)d_out, N, P);
}

// round 9
// speedup vs baseline: 1.1697x; 1.1176x over previous
#include <cuda_runtime.h>
#include <cuda_bf16.h>
#include <cuda_fp16.h>
#include <math.h>
#include <stdint.h>

#define NLVL 16
#define NDENSE 5
#define NHASH (NLVL - NDENSE)
#define TBLSZ (1u << 19)
#define HMASK (TBLSZ - 1u)
#define FSCALE 8192.0f
#define INV_FSCALE (1.0f / 8192.0f)

typedef unsigned long long ull;

struct LvlParams {
    float scale[NLVL];
    int   res[NLVL];
    int   denseBase[NDENSE];
};

// ---- MLP weights in constant memory (layer1 transposed [j][i], PRE-SCALED by
// 1/8192 to undo the fp8 feature scaling; layer2 interleaved pairs). ----
__constant__ __align__(16) float c_dw1t[64 * 32];
__constant__ __align__(16) float c_fw1t[64 * 32];
__constant__ __align__(16) float c_w2a[128];
__constant__ __align__(16) float c_w2b[128];

__device__ __align__(16) float g_wscratch[4352];

// fp8 (e4m3) hash table for levels 5..15: entry = e4m3x2 (2B), scaled x8192.
__device__ __align__(16) unsigned short g_hash8[NHASH * TBLSZ];   // 11.5 MB

// fp8 duplicated-corner dense records, levels 0..4: 8 corners x e4m3x2 = 16B.
#define DENSE_CELLS 532784
__device__ __align__(16) uint4 g_dense8[DENSE_CELLS];             // 8.5 MB

// ---------------- helpers ----------------
__device__ __forceinline__ ull pack2(float lo, float hi) {
    ull r; asm("mov.b64 %0, {%1, %2};" : "=l"(r) : "f"(lo), "f"(hi)); return r;
}
__device__ __forceinline__ float2 unpack2(ull v) {
    float2 r; asm("mov.b64 {%0, %1}, %2;" : "=f"(r.x), "=f"(r.y) : "l"(v)); return r;
}
__device__ __forceinline__ ull fma2(ull a, ull b, ull c) {
    ull d; asm("fma.rn.f32x2 %0, %1, %2, %3;" : "=l"(d) : "l"(a), "l"(b), "l"(c)); return d;
}
__device__ __forceinline__ ull add2(ull a, ull b) {
    ull d; asm("add.rn.f32x2 %0, %1, %2;" : "=l"(d) : "l"(a), "l"(b)); return d;
}
// pack (f0 -> low byte, f1 -> high byte) as e4m3x2
__device__ __forceinline__ unsigned short f8pack(float f0, float f1) {
    unsigned short r;
    asm("cvt.rn.satfinite.e4m3x2.f32 %0, %1, %2;" : "=h"(r) : "f"(f1), "f"(f0));
    return r;
}
// e4m3x2 (2B) -> half2 (exact widening)
__device__ __forceinline__ __half2 f8unpack(unsigned short u) {
    unsigned r;
    asm("cvt.rn.f16x2.e4m3x2 %0, %1;" : "=r"(r) : "h"(u));
    return *reinterpret_cast<__half2*>(&r);
}

// ---------------- prologue kernels ----------------
__global__ void prep_weights_kernel(const float* __restrict__ dw1,
                                    const float* __restrict__ fw1,
                                    const float* __restrict__ dw2,
                                    const float* __restrict__ fw2)
{
    int t = blockIdx.x * 256 + threadIdx.x;   // 0..2047
    if (t < 2048) {
        int i = t & 31, j = t >> 5;           // t = j*32 + i
        g_wscratch[t]        = dw1[i * 64 + j] * INV_FSCALE;
        g_wscratch[2048 + t] = fw1[i * 64 + j] * INV_FSCALE;
    }
    if (t < 64) {
        g_wscratch[4096 + 2 * t + 0] = dw2[t];
        g_wscratch[4096 + 2 * t + 1] = fw2[3 * t + 0];
        g_wscratch[4224 + 2 * t + 0] = fw2[3 * t + 1];
        g_wscratch[4224 + 2 * t + 1] = fw2[3 * t + 2];
    }
}

// Convert hashed-level table entries (contiguous region [5T, 16T)) to e4m3x2.
__global__ void build_hash8_kernel(const float* __restrict__ table)
{
    unsigned t = blockIdx.x * 256 + threadIdx.x;   // one thread = 4 entries
    if (t >= (NHASH * TBLSZ) / 4) return;
    const float4* src = reinterpret_cast<const float4*>(table)
                      + (size_t)NDENSE * (TBLSZ / 2) + (size_t)t * 2;
    float4 a = src[0];
    float4 b = src[1];
    uint2 o;
    o.x = (unsigned)f8pack(a.x * FSCALE, a.y * FSCALE)
        | ((unsigned)f8pack(a.z * FSCALE, a.w * FSCALE) << 16);
    o.y = (unsigned)f8pack(b.x * FSCALE, b.y * FSCALE)
        | ((unsigned)f8pack(b.z * FSCALE, b.w * FSCALE) << 16);
    reinterpret_cast<uint2*>(g_hash8)[t] = o;
}

// Build duplicated-corner fp8 dense records for levels 0..4.
__global__ void build_dense8_kernel(const float* __restrict__ table, LvlParams P)
{
    int id = blockIdx.x * 256 + threadIdx.x;
    if (id >= DENSE_CELLS) return;
    int l = 0;
    #pragma unroll
    for (int k = 1; k < NDENSE; k++)
        if (id >= P.denseBase[k]) l = k;
    int cid = id - P.denseBase[l];
    int R = P.res[l];
    int cx = cid % R;
    int t  = cid / R;
    int cy = t % R;
    int cz = t / R;
    const float2* tl = reinterpret_cast<const float2*>(table) + (size_t)l * TBLSZ;
    unsigned short e[8];
    #pragma unroll
    for (int c = 0; c < 8; c++) {
        int gx = min(cx + ((c >> 2) & 1), R - 1);
        int gy = min(cy + ((c >> 1) & 1), R - 1);
        int gz = min(cz + (c & 1), R - 1);
        float2 v = tl[gx + R * (gy + R * gz)];
        e[c] = f8pack(v.x * FSCALE, v.y * FSCALE);
    }
    uint4 o;
    o.x = (unsigned)e[0] | ((unsigned)e[1] << 16);
    o.y = (unsigned)e[2] | ((unsigned)e[3] << 16);
    o.z = (unsigned)e[4] | ((unsigned)e[5] << 16);
    o.w = (unsigned)e[6] | ((unsigned)e[7] << 16);
    g_dense8[id] = o;
}

// ---------------- main kernel ----------------
__global__ void __launch_bounds__(256, 3)
nerf_field_kernel(const float* __restrict__ points,
                  float* __restrict__ out,
                  int N, LvlParams P)
{
    int gid = blockIdx.x * 256 + threadIdx.x;
    if (gid >= N) return;

    float x = fminf(fmaxf((points[gid * 3 + 0] + 1.0f) * 0.5f, 0.0f), 1.0f);
    float y = fminf(fmaxf((points[gid * 3 + 1] + 1.0f) * 0.5f, 0.0f), 1.0f);
    float z = fminf(fmaxf((points[gid * 3 + 2] + 1.0f) * 0.5f, 0.0f), 1.0f);

    ull encp[16];   // f32x2 feature pairs (scaled x8192; undone by w1 scaling)

    // ---- dense levels 0..4: one 16B fp8 record per cell ----
    #pragma unroll
    for (int l = 0; l < NDENSE; l++) {
        const float sc = P.scale[l];
        const int   R  = P.res[l];
        float px = x * sc + 0.5f, py = y * sc + 0.5f, pz = z * sc + 0.5f;
        float fx = floorf(px), fy = floorf(py), fz = floorf(pz);
        float wx = px - fx,    wy = py - fy,    wz = pz - fz;
        int cell = (int)fx + R * ((int)fy + R * (int)fz);

        uint4 q = __ldg(&g_dense8[P.denseBase[l] + cell]);

        float wx0 = 1.0f - wx, wy0 = 1.0f - wy, wz0 = 1.0f - wz;
        float w00 = wy0 * wz0, w01 = wy0 * wz, w10 = wy * wz0, w11 = wy * wz;

        __half2 acc0 = __float2half2_rn(0.0f);
        __half2 acc1 = __float2half2_rn(0.0f);
        acc0 = __hfma2(__float2half2_rn(wx0 * w00), f8unpack((unsigned short)(q.x      )), acc0);
        acc1 = __hfma2(__float2half2_rn(wx0 * w01), f8unpack((unsigned short)(q.x >> 16)), acc1);
        acc0 = __hfma2(__float2half2_rn(wx0 * w10), f8unpack((unsigned short)(q.y      )), acc0);
        acc1 = __hfma2(__float2half2_rn(wx0 * w11), f8unpack((unsigned short)(q.y >> 16)), acc1);
        acc0 = __hfma2(__float2half2_rn(wx  * w00), f8unpack((unsigned short)(q.z      )), acc0);
        acc1 = __hfma2(__float2half2_rn(wx  * w01), f8unpack((unsigned short)(q.z >> 16)), acc1);
        acc0 = __hfma2(__float2half2_rn(wx  * w10), f8unpack((unsigned short)(q.w      )), acc0);
        acc1 = __hfma2(__float2half2_rn(wx  * w11), f8unpack((unsigned short)(q.w >> 16)), acc1);
        float2 e = __half22float2(__hadd2(acc0, acc1));
        encp[l] = pack2(e.x, e.y);
    }

    // ---- hashed levels 5..15: fp8 entries, LDG.64 covers the x-pair 75% ----
    #pragma unroll
    for (int l = NDENSE; l < NLVL; l++) {
        const float sc = P.scale[l];
        const int   R  = P.res[l];
        float px = x * sc + 0.5f, py = y * sc + 0.5f, pz = z * sc + 0.5f;
        float fx = floorf(px), fy = floorf(py), fz = floorf(pz);
        float wx = px - fx,    wy = py - fy,    wz = pz - fz;
        int ix = (int)fx, iy = (int)fy, iz = (int)fz;

        unsigned x0 = (unsigned)ix;
        unsigned x1 = (unsigned)min(ix + 1, R - 1);
        unsigned hyv[2] = {(unsigned)iy * 2654435761u,
                           (unsigned)min(iy + 1, R - 1) * 2654435761u};
        unsigned hzv[2] = {(unsigned)iz * 805459861u,
                           (unsigned)min(iz + 1, R - 1) * 805459861u};

        const uint2* t8 = reinterpret_cast<const uint2*>(g_hash8)
                        + (size_t)(l - NDENSE) * (TBLSZ / 4);
        const unsigned* t4 = reinterpret_cast<const unsigned*>(g_hash8)
                           + (size_t)(l - NDENSE) * (TBLSZ / 2);

        float wwy[2] = {1.0f - wy, wy};
        float wwz[2] = {1.0f - wz, wz};
        float wA = 1.0f - wx, wB = wx;
        __half2 accA = __float2half2_rn(0.0f);
        __half2 accB = __float2half2_rn(0.0f);

        #pragma unroll
        for (int yi = 0; yi < 2; yi++) {
            #pragma unroll
            for (int zi = 0; zi < 2; zi++) {
                unsigned h  = hyv[yi] ^ hzv[zi];
                unsigned iA = (h ^ x0) & HMASK;
                unsigned iB = (h ^ x1) & HMASK;
                unsigned bA = iA >> 2;
                uint2 q = __ldg(t8 + bA);
                unsigned wordA = (iA & 2) ? q.y : q.x;
                unsigned short hwA = (unsigned short)(wordA >> ((iA & 1) << 4));
                unsigned wordB;
                if ((iB >> 2) == bA) {
                    wordB = (iB & 2) ? q.y : q.x;
                } else {
                    wordB = __ldg(t4 + (iB >> 1));    // 25% of lanes
                }
                unsigned short hwB = (unsigned short)(wordB >> ((iB & 1) << 4));

                float wyz = wwy[yi] * wwz[zi];
                accA = __hfma2(__float2half2_rn(wyz * wA), f8unpack(hwA), accA);
                accB = __hfma2(__float2half2_rn(wyz * wB), f8unpack(hwB), accB);
            }
        }
        float2 e = __half22float2(__hadd2(accA, accB));
        encp[l] = pack2(e.x, e.y);
    }

    // ---- two 2-layer bias-free MLPs (constant-port weights, f32x2 FMAs) ----
    const ulonglong2* wd4 = reinterpret_cast<const ulonglong2*>(c_dw1t);
    const ulonglong2* wf4 = reinterpret_cast<const ulonglong2*>(c_fw1t);
    const ull* w2a = reinterpret_cast<const ull*>(c_w2a);
    const ull* w2b = reinterpret_cast<const ull*>(c_w2b);

    ull dc0 = 0ull, dc1 = 0ull;
    ull cc0 = 0ull, cc1 = 0ull;
    #pragma unroll 4
    for (int j = 0; j < 64; j++) {
        ull s2a = 0ull, s2b = 0ull, t2a = 0ull, t2b = 0ull;
        #pragma unroll
        for (int k = 0; k < 4; k++) {
            ulonglong2 wv0 = wd4[j * 8 + 2 * k + 0];
            ulonglong2 fv0 = wf4[j * 8 + 2 * k + 0];
            ulonglong2 wv1 = wd4[j * 8 + 2 * k + 1];
            ulonglong2 fv1 = wf4[j * 8 + 2 * k + 1];
            s2a = fma2(encp[4 * k + 0], wv0.x, s2a);
            t2a = fma2(encp[4 * k + 0], fv0.x, t2a);
            s2b = fma2(encp[4 * k + 1], wv0.y, s2b);
            t2b = fma2(encp[4 * k + 1], fv0.y, t2b);
            s2a = fma2(encp[4 * k + 2], wv1.x, s2a);
            t2a = fma2(encp[4 * k + 2], fv1.x, t2a);
            s2b = fma2(encp[4 * k + 3], wv1.y, s2b);
            t2b = fma2(encp[4 * k + 3], fv1.y, t2b);
        }
        float2 sv = unpack2(add2(s2a, s2b));
        float2 tv = unpack2(add2(t2a, t2b));
        float s = fmaxf(sv.x + sv.y, 0.0f);
        float t = fmaxf(tv.x + tv.y, 0.0f);
        if (j & 1) {
            dc1 = fma2(pack2(s, t), w2a[j], dc1);
            cc1 = fma2(pack2(t, t), w2b[j], cc1);
        } else {
            dc0 = fma2(pack2(s, t), w2a[j], dc0);
            cc0 = fma2(pack2(t, t), w2b[j], cc0);
        }
    }

    float2 dcv = unpack2(add2(dc0, dc1));
    float2 ccv = unpack2(add2(cc0, cc1));
    float dacc = dcv.x, c0 = dcv.y, c1 = ccv.x, c2 = ccv.y;

    float density = fmaxf(dacc, 0.0f) + log1pf(expf(-fabsf(dacc)));
    float r0 = 1.0f / (1.0f + expf(-c0));
    float r1 = 1.0f / (1.0f + expf(-c1));
    float r2 = 1.0f / (1.0f + expf(-c2));

    out[gid * 3 + 0] = r0;
    out[gid * 3 + 1] = r1;
    out[gid * 3 + 2] = r2;
    out[(size_t)3 * N + gid] = density;
}

extern "C" void kernel_launch(void* const* d_in, const int* in_sizes, int n_in,
                              void* d_out, int out_size)
{
    const float* points = (const float*)d_in[0];
    const float* table  = (const float*)d_in[1];
    const float* dw1    = (const float*)d_in[2];
    const float* dw2    = (const float*)d_in[3];
    const float* fw1    = (const float*)d_in[4];
    const float* fw2    = (const float*)d_in[5];
    int N = in_sizes[0] / 3;

    LvlParams P;
    int cellBase = 0;
    for (int l = 0; l < NLVL; l++) {
        double sc = 16.0 * pow(1.447269237440378, (double)l) - 1.0;
        int res = (int)ceil(sc) + 1;
        P.scale[l] = (float)sc;
        P.res[l] = res;
        if (l < NDENSE) { P.denseBase[l] = cellBase; cellBase += res * res * res; }
    }

    prep_weights_kernel<<<8, 256>>>(dw1, fw1, dw2, fw2);
    build_hash8_kernel<<<(NHASH * TBLSZ / 4 + 255) / 256, 256>>>(table);
    build_dense8_kernel<<<(DENSE_CELLS + 255) / 256, 256>>>(table, P);

    void* src = nullptr;
    cudaGetSymbolAddress(&src, g_wscratch);
    cudaMemcpyToSymbolAsync(c_dw1t, src, 2048 * sizeof(float), 0,
                            cudaMemcpyDeviceToDevice, 0);
    cudaMemcpyToSymbolAsync(c_fw1t, (const char*)src + 2048 * sizeof(float),
                            2048 * sizeof(float), 0, cudaMemcpyDeviceToDevice, 0);
    cudaMemcpyToSymbolAsync(c_w2a, (const char*)src + 4096 * sizeof(float),
                            128 * sizeof(float), 0, cudaMemcpyDeviceToDevice, 0);
    cudaMemcpyToSymbolAsync(c_w2b, (const char*)src + 4224 * sizeof(float),
                            128 * sizeof(float), 0, cudaMemcpyDeviceToDevice, 0);

    int blocks = (N + 255) / 256;
    nerf_field_kernel<<<blocks, 256>>>(points, (float*)d_out, N, P);
}

// round 10
// speedup vs baseline: 1.5076x; 1.2889x over previous
#include <cuda_runtime.h>
#include <cuda_bf16.h>
#include <cuda_fp16.h>
#include <math.h>
#include <stdint.h>

#define NLVL 16
#define NDENSE 5
#define NHASH (NLVL - NDENSE)
#define TBLSZ (1u << 19)
#define HMASK (TBLSZ - 1u)
#define FSCALE 8192.0f
#define INV_FSCALE (1.0f / 8192.0f)

typedef unsigned long long ull;

struct LvlParams {
    float scale[NLVL];
    int   res[NLVL];
    int   denseBase[NDENSE];
};

// layer-2 weights: [0:64) dw2, [64:128) fw2 col0, [128:192) col1, [192:256) col2
__constant__ float c_w2[256];

__device__ __align__(16) float g_wscratch[256];
// W1 combined+transposed bf16 [128 hidden][32 feat], scaled 1/FSCALE:
// rows 0-63 = dw1^T, rows 64-127 = fw1^T
__device__ __align__(16) unsigned short g_w1tb[128 * 32];

// fp8 (e4m3) hash table for levels 5..15 (scaled x8192)
__device__ __align__(16) unsigned short g_hash8[NHASH * TBLSZ];
// fp8 duplicated-corner dense records, levels 0..4
#define DENSE_CELLS 532784
__device__ __align__(16) uint4 g_dense8[DENSE_CELLS];

// ---------------- helpers ----------------
__device__ __forceinline__ uint32_t smem_u32(const void* p) {
    uint32_t a;
    asm("{ .reg .u64 t; cvta.to.shared.u64 t, %1; cvt.u32.u64 %0, t; }" : "=r"(a) : "l"(p));
    return a;
}
__device__ __forceinline__ unsigned short f8pack(float f0, float f1) {
    unsigned short r;
    asm("cvt.rn.satfinite.e4m3x2.f32 %0, %1, %2;" : "=h"(r) : "f"(f1), "f"(f0));
    return r;
}
__device__ __forceinline__ __half2 f8unpack(unsigned short u) {
    unsigned r;
    asm("cvt.rn.f16x2.e4m3x2 %0, %1;" : "=r"(r) : "h"(u));
    return *reinterpret_cast<__half2*>(&r);
}
__device__ __forceinline__ unsigned bf16x2_of(float lo, float hi) {
    unsigned r;
    asm("cvt.rn.bf16x2.f32 %0, %1, %2;" : "=r"(r) : "f"(hi), "f"(lo));
    return r;
}
__device__ __forceinline__ void ldsm_x4(uint32_t addr, uint32_t& r0, uint32_t& r1,
                                        uint32_t& r2, uint32_t& r3) {
    asm volatile("ldmatrix.sync.aligned.m8n8.x4.shared.b16 {%0,%1,%2,%3}, [%4];"
                 : "=r"(r0), "=r"(r1), "=r"(r2), "=r"(r3) : "r"(addr));
}
__device__ __forceinline__ void mma_bf16(float& d0, float& d1, float& d2, float& d3,
                                         uint32_t a0, uint32_t a1, uint32_t a2, uint32_t a3,
                                         uint32_t b0, uint32_t b1) {
    asm volatile(
        "mma.sync.aligned.m16n8k16.row.col.f32.bf16.bf16.f32 "
        "{%0,%1,%2,%3}, {%4,%5,%6,%7}, {%8,%9}, {%0,%1,%2,%3};"
        : "+f"(d0), "+f"(d1), "+f"(d2), "+f"(d3)
        : "r"(a0), "r"(a1), "r"(a2), "r"(a3), "r"(b0), "r"(b1));
}

// ---------------- prologue kernels ----------------
__global__ void prep_weights_kernel(const float* __restrict__ dw1,
                                    const float* __restrict__ fw1,
                                    const float* __restrict__ dw2,
                                    const float* __restrict__ fw2)
{
    int t = blockIdx.x * 256 + threadIdx.x;   // 0..4095
    if (t < 4096) {
        int j = t >> 5, k = t & 31;
        float v = (j < 64 ? dw1[k * 64 + j] : fw1[k * 64 + (j - 64)]) * INV_FSCALE;
        g_w1tb[t] = __bfloat16_as_ushort(__float2bfloat16(v));
    }
    if (t < 64) {
        g_wscratch[t]       = dw2[t];
        g_wscratch[64 + t]  = fw2[3 * t + 0];
        g_wscratch[128 + t] = fw2[3 * t + 1];
        g_wscratch[192 + t] = fw2[3 * t + 2];
    }
}

__global__ void build_hash8_kernel(const float* __restrict__ table)
{
    unsigned t = blockIdx.x * 256 + threadIdx.x;
    if (t >= (NHASH * TBLSZ) / 4) return;
    const float4* src = reinterpret_cast<const float4*>(table)
                      + (size_t)NDENSE * (TBLSZ / 2) + (size_t)t * 2;
    float4 a = src[0];
    float4 b = src[1];
    uint2 o;
    o.x = (unsigned)f8pack(a.x * FSCALE, a.y * FSCALE)
        | ((unsigned)f8pack(a.z * FSCALE, a.w * FSCALE) << 16);
    o.y = (unsigned)f8pack(b.x * FSCALE, b.y * FSCALE)
        | ((unsigned)f8pack(b.z * FSCALE, b.w * FSCALE) << 16);
    reinterpret_cast<uint2*>(g_hash8)[t] = o;
}

__global__ void build_dense8_kernel(const float* __restrict__ table, LvlParams P)
{
    int id = blockIdx.x * 256 + threadIdx.x;
    if (id >= DENSE_CELLS) return;
    int l = 0;
    #pragma unroll
    for (int k = 1; k < NDENSE; k++)
        if (id >= P.denseBase[k]) l = k;
    int cid = id - P.denseBase[l];
    int R = P.res[l];
    int cx = cid % R;
    int t  = cid / R;
    int cy = t % R;
    int cz = t / R;
    const float2* tl = reinterpret_cast<const float2*>(table) + (size_t)l * TBLSZ;
    unsigned short e[8];
    #pragma unroll
    for (int c = 0; c < 8; c++) {
        int gx = min(cx + ((c >> 2) & 1), R - 1);
        int gy = min(cy + ((c >> 1) & 1), R - 1);
        int gz = min(cz + (c & 1), R - 1);
        float2 v = tl[gx + R * (gy + R * gz)];
        e[c] = f8pack(v.x * FSCALE, v.y * FSCALE);
    }
    uint4 o;
    o.x = (unsigned)e[0] | ((unsigned)e[1] << 16);
    o.y = (unsigned)e[2] | ((unsigned)e[3] << 16);
    o.z = (unsigned)e[4] | ((unsigned)e[5] << 16);
    o.w = (unsigned)e[6] | ((unsigned)e[7] << 16);
    g_dense8[id] = o;
}

// ---------------- main kernel ----------------
// Each warp owns 32 points; MLP via mma.sync (HMMA) on bf16.
__global__ void __launch_bounds__(256, 3)
nerf_field_kernel(const float* __restrict__ points,
                  float* __restrict__ out,
                  int N, LvlParams P)
{
    // stride 80B: 16B-aligned rows, conflict-free LDSM phases
    __shared__ __align__(16) unsigned char s_w1[128 * 80];
    __shared__ __align__(16) unsigned char s_enc[256 * 80];

    const int tid  = threadIdx.x;
    const int lane = tid & 31;
    const int warp = tid >> 5;
    const int g = lane >> 2;     // row-group within fragments
    const int q = lane & 3;      // col-group (quad id)

    // stage W1 (128 rows x 64B) into 80B-stride smem
    if (tid < 128) {
        const uint4* src = reinterpret_cast<const uint4*>(g_w1tb) + tid * 4;
        uint4* dst = reinterpret_cast<uint4*>(s_w1 + tid * 80);
        dst[0] = src[0]; dst[1] = src[1]; dst[2] = src[2]; dst[3] = src[3];
    }
    __syncthreads();

    int gid = blockIdx.x * 256 + tid;
    int gc = min(gid, N - 1);

    float x = fminf(fmaxf((points[gc * 3 + 0] + 1.0f) * 0.5f, 0.0f), 1.0f);
    float y = fminf(fmaxf((points[gc * 3 + 1] + 1.0f) * 0.5f, 0.0f), 1.0f);
    float z = fminf(fmaxf((points[gc * 3 + 2] + 1.0f) * 0.5f, 0.0f), 1.0f);

    unsigned char* myrow = s_enc + tid * 80;

    // ---- dense levels 0..4 ----
    #pragma unroll
    for (int l = 0; l < NDENSE; l++) {
        const float sc = P.scale[l];
        const int   R  = P.res[l];
        float px = x * sc + 0.5f, py = y * sc + 0.5f, pz = z * sc + 0.5f;
        float fx = floorf(px), fy = floorf(py), fz = floorf(pz);
        float wx = px - fx,    wy = py - fy,    wz = pz - fz;
        int cell = (int)fx + R * ((int)fy + R * (int)fz);

        uint4 qd = __ldg(&g_dense8[P.denseBase[l] + cell]);

        float wx0 = 1.0f - wx, wy0 = 1.0f - wy, wz0 = 1.0f - wz;
        float w00 = wy0 * wz0, w01 = wy0 * wz, w10 = wy * wz0, w11 = wy * wz;

        __half2 a0 = __float2half2_rn(0.0f);
        __half2 a1 = __float2half2_rn(0.0f);
        a0 = __hfma2(__float2half2_rn(wx0 * w00), f8unpack((unsigned short)(qd.x      )), a0);
        a1 = __hfma2(__float2half2_rn(wx0 * w01), f8unpack((unsigned short)(qd.x >> 16)), a1);
        a0 = __hfma2(__float2half2_rn(wx0 * w10), f8unpack((unsigned short)(qd.y      )), a0);
        a1 = __hfma2(__float2half2_rn(wx0 * w11), f8unpack((unsigned short)(qd.y >> 16)), a1);
        a0 = __hfma2(__float2half2_rn(wx  * w00), f8unpack((unsigned short)(qd.z      )), a0);
        a1 = __hfma2(__float2half2_rn(wx  * w01), f8unpack((unsigned short)(qd.z >> 16)), a1);
        a0 = __hfma2(__float2half2_rn(wx  * w10), f8unpack((unsigned short)(qd.w      )), a0);
        a1 = __hfma2(__float2half2_rn(wx  * w11), f8unpack((unsigned short)(qd.w >> 16)), a1);
        float2 e = __half22float2(__hadd2(a0, a1));
        *reinterpret_cast<unsigned*>(myrow + l * 4) = bf16x2_of(e.x, e.y);
    }

    // ---- hashed levels 5..15 ----
    #pragma unroll
    for (int l = NDENSE; l < NLVL; l++) {
        const float sc = P.scale[l];
        const int   R  = P.res[l];
        float px = x * sc + 0.5f, py = y * sc + 0.5f, pz = z * sc + 0.5f;
        float fx = floorf(px), fy = floorf(py), fz = floorf(pz);
        float wx = px - fx,    wy = py - fy,    wz = pz - fz;
        int ix = (int)fx, iy = (int)fy, iz = (int)fz;

        unsigned x0 = (unsigned)ix;
        unsigned x1 = (unsigned)min(ix + 1, R - 1);
        unsigned hyv[2] = {(unsigned)iy * 2654435761u,
                           (unsigned)min(iy + 1, R - 1) * 2654435761u};
        unsigned hzv[2] = {(unsigned)iz * 805459861u,
                           (unsigned)min(iz + 1, R - 1) * 805459861u};

        const uint2* t8 = reinterpret_cast<const uint2*>(g_hash8)
                        + (size_t)(l - NDENSE) * (TBLSZ / 4);
        const unsigned* t4 = reinterpret_cast<const unsigned*>(g_hash8)
                           + (size_t)(l - NDENSE) * (TBLSZ / 2);

        float wwy[2] = {1.0f - wy, wy};
        float wwz[2] = {1.0f - wz, wz};
        float wA = 1.0f - wx, wB = wx;
        __half2 accA = __float2half2_rn(0.0f);
        __half2 accB = __float2half2_rn(0.0f);

        #pragma unroll
        for (int yi = 0; yi < 2; yi++) {
            #pragma unroll
            for (int zi = 0; zi < 2; zi++) {
                unsigned h  = hyv[yi] ^ hzv[zi];
                unsigned iA = (h ^ x0) & HMASK;
                unsigned iB = (h ^ x1) & HMASK;
                unsigned bA = iA >> 2;
                uint2 qh = __ldg(t8 + bA);
                unsigned wordA = (iA & 2) ? qh.y : qh.x;
                unsigned short hwA = (unsigned short)(wordA >> ((iA & 1) << 4));
                unsigned wordB;
                if ((iB >> 2) == bA) {
                    wordB = (iB & 2) ? qh.y : qh.x;
                } else {
                    wordB = __ldg(t4 + (iB >> 1));
                }
                unsigned short hwB = (unsigned short)(wordB >> ((iB & 1) << 4));

                float wyz = wwy[yi] * wwz[zi];
                accA = __hfma2(__float2half2_rn(wyz * wA), f8unpack(hwA), accA);
                accB = __hfma2(__float2half2_rn(wyz * wB), f8unpack(hwB), accB);
            }
        }
        float2 e = __half22float2(__hadd2(accA, accB));
        *reinterpret_cast<unsigned*>(myrow + l * 4) = bf16x2_of(e.x, e.y);
    }

    __syncwarp();

    // ---- load A fragments: 2 M-tiles x 2 K-tiles, m16k16 each ----
    uint32_t sab = smem_u32(s_enc) + (warp * 32) * 80;
    uint32_t swb = smem_u32(s_w1);
    uint32_t af[2][2][4];
    #pragma unroll
    for (int m = 0; m < 2; m++) {
        #pragma unroll
        for (int k = 0; k < 2; k++) {
            uint32_t addr = sab + (m * 16 + (lane & 15)) * 80 + k * 32 + ((lane >> 4) << 4);
            ldsm_x4(addr, af[m][k][0], af[m][k][1], af[m][k][2], af[m][k][3]);
        }
    }

    // ---- MMA over 16 n8-tiles with fused ReLU + layer-2 ----
    // accumulators indexed by row idx: 0->g, 1->g+8, 2->g+16, 3->g+24
    float dacc[4] = {0, 0, 0, 0};
    float c0[4] = {0, 0, 0, 0}, c1[4] = {0, 0, 0, 0}, c2[4] = {0, 0, 0, 0};

    #pragma unroll
    for (int n = 0; n < 16; n++) {
        uint32_t b0, b1, b2, b3;
        uint32_t baddr = swb + (8 * n + (lane & 7)) * 80 + ((lane >> 3) << 4);
        ldsm_x4(baddr, b0, b1, b2, b3);

        #pragma unroll
        for (int m = 0; m < 2; m++) {
            float d0 = 0, d1 = 0, d2 = 0, d3 = 0;
            mma_bf16(d0, d1, d2, d3,
                     af[m][0][0], af[m][0][1], af[m][0][2], af[m][0][3], b0, b1);
            mma_bf16(d0, d1, d2, d3,
                     af[m][1][0], af[m][1][1], af[m][1][2], af[m][1][3], b2, b3);
            float r0 = fmaxf(d0, 0.0f), r1 = fmaxf(d1, 0.0f);
            float r2 = fmaxf(d2, 0.0f), r3 = fmaxf(d3, 0.0f);
            if (n < 8) {
                int j0 = 8 * n + 2 * q;
                float w0 = c_w2[j0], w1 = c_w2[j0 + 1];
                dacc[2 * m + 0] += r0 * w0 + r1 * w1;
                dacc[2 * m + 1] += r2 * w0 + r3 * w1;
            } else {
                int j0 = 8 * (n - 8) + 2 * q;
                float wa0 = c_w2[64 + j0],  wa1 = c_w2[64 + j0 + 1];
                float wb0 = c_w2[128 + j0], wb1 = c_w2[128 + j0 + 1];
                float wc0 = c_w2[192 + j0], wc1 = c_w2[192 + j0 + 1];
                c0[2 * m + 0] += r0 * wa0 + r1 * wa1;
                c0[2 * m + 1] += r2 * wa0 + r3 * wa1;
                c1[2 * m + 0] += r0 * wb0 + r1 * wb1;
                c1[2 * m + 1] += r2 * wb0 + r3 * wb1;
                c2[2 * m + 0] += r0 * wc0 + r1 * wc1;
                c2[2 * m + 1] += r2 * wc0 + r3 * wc1;
            }
        }
    }

    // ---- reduce across the 4 lanes of each quad (cols) ----
    #pragma unroll
    for (int i = 0; i < 4; i++) {
        dacc[i] += __shfl_xor_sync(0xFFFFFFFF, dacc[i], 1);
        dacc[i] += __shfl_xor_sync(0xFFFFFFFF, dacc[i], 2);
        c0[i]   += __shfl_xor_sync(0xFFFFFFFF, c0[i], 1);
        c0[i]   += __shfl_xor_sync(0xFFFFFFFF, c0[i], 2);
        c1[i]   += __shfl_xor_sync(0xFFFFFFFF, c1[i], 1);
        c1[i]   += __shfl_xor_sync(0xFFFFFFFF, c1[i], 2);
        c2[i]   += __shfl_xor_sync(0xFFFFFFFF, c2[i], 1);
        c2[i]   += __shfl_xor_sync(0xFFFFFFFF, c2[i], 2);
    }

    // ---- activations + stores (quad leaders handle 4 rows each) ----
    if (q == 0) {
        int base = blockIdx.x * 256 + warp * 32;
        #pragma unroll
        for (int i = 0; i < 4; i++) {
            int pt = base + g + 16 * (i >> 1) + 8 * (i & 1);
            if (pt < N) {
                float density = fmaxf(dacc[i], 0.0f) + log1pf(expf(-fabsf(dacc[i])));
                out[pt * 3 + 0] = 1.0f / (1.0f + expf(-c0[i]));
                out[pt * 3 + 1] = 1.0f / (1.0f + expf(-c1[i]));
                out[pt * 3 + 2] = 1.0f / (1.0f + expf(-c2[i]));
                out[(size_t)3 * N + pt] = density;
            }
        }
    }
}

extern "C" void kernel_launch(void* const* d_in, const int* in_sizes, int n_in,
                              void* d_out, int out_size)
{
    const float* points = (const float*)d_in[0];
    const float* table  = (const float*)d_in[1];
    const float* dw1    = (const float*)d_in[2];
    const float* dw2    = (const float*)d_in[3];
    const float* fw1    = (const float*)d_in[4];
    const float* fw2    = (const float*)d_in[5];
    int N = in_sizes[0] / 3;

    LvlParams P;
    int cellBase = 0;
    for (int l = 0; l < NLVL; l++) {
        double sc = 16.0 * pow(1.447269237440378, (double)l) - 1.0;
        int res = (int)ceil(sc) + 1;
        P.scale[l] = (float)sc;
        P.res[l] = res;
        if (l < NDENSE) { P.denseBase[l] = cellBase; cellBase += res * res * res; }
    }

    prep_weights_kernel<<<16, 256>>>(dw1, fw1, dw2, fw2);
    build_hash8_kernel<<<(NHASH * TBLSZ / 4 + 255) / 256, 256>>>(table);
    build_dense8_kernel<<<(DENSE_CELLS + 255) / 256, 256>>>(table, P);

    void* src = nullptr;
    cudaGetSymbolAddress(&src, g_wscratch);
    cudaMemcpyToSymbolAsync(c_w2, src, 256 * sizeof(float), 0,
                            cudaMemcpyDeviceToDevice, 0);

    int blocks = (N + 255) / 256;
    nerf_field_kernel<<<blocks, 256>>>(points, (float*)d_out, N, P);
}